// round 15
// baseline (speedup 1.0000x reference)
#include <cuda_runtime.h>
#include <cstdint>

// TransposeTDLayer via tf32 mma.sync + cp.async, K=16-stage QUAD buffer,
// issue-lead 2, XOR-swizzled packed smem, PERSISTENT CTAs: grid 592 = 4/SM,
// each CTA streams chunks of up to two positions (i, i+592) through one
// uninterrupted pipeline; epilogue of pos0 overlaps loads of pos1.
// y[b,p,o] = bias[p,o] + sum_{(k,l):k+2l=p} sum_ci W[k,l,o,ci] * x[b,l,ci]
// tf32 rounding via +0x1000 (bit-exact vs cvt.rna.tf32, validated round 10).

#define BATCH 64
#define LIN   512
#define CIN   128
#define COUT  128
#define OUTP  1030
#define GRID  592     // 4 CTAs x 148 SMs -> exactly one wave

#define A_OFF   0
#define A_BYTES 8192                       // 128 rows x 64B packed
#define B_OFF   A_BYTES
#define B_BYTES 4096                       // 64 rows x 64B packed
#define BUF_BYTES (A_BYTES + B_BYTES)      // 12288
#define NSTAGE  4
#define SMEM_TOTAL (NSTAGE * BUF_BYTES)    // 49152/CTA -> 4 CTAs/SM

static __device__ __forceinline__ uint32_t smem_u32(const void* p) {
    uint32_t a;
    asm("{ .reg .u64 t; cvta.to.shared.u64 t, %1; cvt.u32.u64 %0, t; }"
        : "=r"(a) : "l"(p));
    return a;
}

static __device__ __forceinline__ void mma_tf32(
    float* c, const uint32_t* a, const uint32_t* b)
{
    asm volatile(
        "mma.sync.aligned.m16n8k8.row.col.f32.tf32.tf32.f32 "
        "{%0,%1,%2,%3}, {%4,%5,%6,%7}, {%8,%9}, {%0,%1,%2,%3};"
        : "+f"(c[0]), "+f"(c[1]), "+f"(c[2]), "+f"(c[3])
        : "r"(a[0]), "r"(a[1]), "r"(a[2]), "r"(a[3]), "r"(b[0]), "r"(b[1]));
}

static __device__ __forceinline__ void ldsm_x4(uint32_t* r, uint32_t addr) {
    asm volatile("ldmatrix.sync.aligned.m8n8.x4.shared.b16 {%0,%1,%2,%3}, [%4];"
                 : "=r"(r[0]), "=r"(r[1]), "=r"(r[2]), "=r"(r[3]) : "r"(addr));
}

// tf32 round-to-nearest via +half-ulp; tensor core truncates low 13 bits.
static __device__ __forceinline__ uint32_t round_tf32(uint32_t v) {
    return v + 0x1000u;
}

static __device__ __forceinline__ void cpasync16(uint32_t dst, const void* src) {
    asm volatile("cp.async.cg.shared.global [%0], [%1], 16;"
                 :: "r"(dst), "l"(src) : "memory");
}
#define CP_COMMIT() asm volatile("cp.async.commit_group;" ::: "memory")
#define CP_WAIT2()  asm volatile("cp.async.wait_group 2;" ::: "memory")

// swizzled byte offset of 16B granule g (0..3) in 64B row r
static __device__ __forceinline__ uint32_t sw_off(int r, int g) {
    return (uint32_t)((r >> 1) * 128 + (((g + (r & 1) * 4) ^ ((r >> 1) & 7)) << 4));
}

__global__ void __launch_bounds__(256, 4)
tdconv_tf32pp_kernel(const float* __restrict__ x,
                     const float* __restrict__ w,
                     const float* __restrict__ bias,
                     float* __restrict__ y)
{
    extern __shared__ char smem[];
    const uint32_t sbase = smem_u32(smem);

    const int tid  = threadIdx.x;
    const int wid  = tid >> 5;
    const int lane = tid & 31;

    const int mrow = (wid >> 1) * 32;   // cout base (0,32,64,96)
    const int ncol = (wid & 1) * 32;    // batch base (0,32)

    // two positions per CTA: p_a = bid, p_b = bid + GRID (if < OUTP)
    const int p_a = blockIdx.x;
    const int p_b = p_a + GRID;

    const int par_a = p_a & 1;
    const int m_a   = p_a >> 1;
    int j0_a = m_a - (LIN - 1); if (j0_a < 0) j0_a = 0;
    const int j1_a = m_a < 3 ? m_a : 3;
    const int n1 = 8 * (j1_a - j0_a + 1);

    int par_b = 0, m_b = 0, j0_b = 0, n2 = 0;
    if (p_b < OUTP) {
        par_b = p_b & 1;
        m_b   = p_b >> 1;
        j0_b = m_b - (LIN - 1); if (j0_b < 0) j0_b = 0;
        const int j1_b = m_b < 3 ? m_b : 3;
        n2 = 8 * (j1_b - j0_b + 1);
    }
    const int ntot = n1 + n2;

    // producer decomposition: thread -> (row cr 0..63, granule cg 0..3)
    const int cr = tid >> 2;
    const int cg = tid & 3;
    const uint32_t d0 = sw_off(cr, cg);

    // issue cp.async for global chunk c into buf[c&3]
    auto issue_chunk = [&](int c) {
        if (c < ntot) {
            int cc, par, mm, jj0;
            if (c < n1) { cc = c;      par = par_a; mm = m_a; jj0 = j0_a; }
            else        { cc = c - n1; par = par_b; mm = m_b; jj0 = j0_b; }
            const int j = jj0 + (cc >> 3);
            const int l = mm - j;
            const int k = par + 2 * j;
            const int kh = (cc & 7) * 16;
            const float* __restrict__ wp =
                w + (size_t)(k * LIN + l) * (COUT * CIN)
                  + (size_t)cr * CIN + kh + cg * 4;
            const float* __restrict__ xp =
                x + ((size_t)cr * LIN + l) * CIN + kh + cg * 4;
            const uint32_t buf = sbase + (uint32_t)(c & 3) * BUF_BYTES;
            cpasync16(buf + A_OFF + d0,        wp);
            cpasync16(buf + A_OFF + d0 + 4096, wp + 64 * CIN);
            cpasync16(buf + B_OFF + d0,        xp);
        }
        CP_COMMIT();   // uniform group counting
    };

    // consumer (ldmatrix) lane constants
    const int q   = (lane & 7) + ((lane >> 3) & 1) * 8;   // A row-in-tile
    const int hi  = lane >> 4;
    const uint32_t a_line = (uint32_t)(mrow / 2 + (q >> 1)) * 128;
    const int a_add = (q & 1) * 4, a_s = q >> 1;

    const int qb  = (lane & 7) + (lane >> 4) * 8;         // B row-in-tile
    const int hb  = (lane >> 3) & 1;
    const uint32_t b_line = (uint32_t)(ncol / 2 + (qb >> 1)) * 128;
    const int b_add = (qb & 1) * 4, b_s = qb >> 1;

    const int g = lane >> 2;
    const int t = lane & 3;

    float acc[2][4][4];
    auto init_acc = [&](int p) {
        #pragma unroll
        for (int mi = 0; mi < 2; mi++) {
            const float b_g  = bias[p * COUT + mrow + mi * 16 + g];
            const float b_g8 = bias[p * COUT + mrow + mi * 16 + g + 8];
            #pragma unroll
            for (int ni = 0; ni < 4; ni++) {
                acc[mi][ni][0] = b_g;  acc[mi][ni][1] = b_g;
                acc[mi][ni][2] = b_g8; acc[mi][ni][3] = b_g8;
            }
        }
    };
    auto epilogue = [&](int p) {      // register-only drain; no sync needed
        #pragma unroll
        for (int mi = 0; mi < 2; mi++) {
            const int o0 = mrow + mi * 16 + g;
            const int o8 = o0 + 8;
            #pragma unroll
            for (int ni = 0; ni < 4; ni++) {
                const int b0 = ncol + ni * 8 + 2 * t;
                float* y0 = y + ((size_t)b0 * OUTP + p) * COUT;
                float* y1 = y0 + (size_t)OUTP * COUT;
                y0[o0] = acc[mi][ni][0];
                y1[o0] = acc[mi][ni][1];
                y0[o8] = acc[mi][ni][2];
                y1[o8] = acc[mi][ni][3];
            }
        }
    };

    init_acc(p_a);

    // prologue: 3 chunks in flight
    issue_chunk(0);
    issue_chunk(1);
    issue_chunk(2);

    for (int c = 0; c < ntot; c++) {
        CP_WAIT2();               // chunk c retired (c+1, c+2 pending ok)
        __syncthreads();          // chunk c visible; buf[(c+3)&3] reusable

        issue_chunk(c + 3);       // refill BEFORE compute

        const uint32_t buf = sbase + (uint32_t)(c & 3) * BUF_BYTES;
        const uint32_t ab = buf + A_OFF + a_line;
        const uint32_t bb = buf + B_OFF + b_line;

        #pragma unroll
        for (int ks = 0; ks < 2; ks++) {           // 2 k8-steps over K=16
            const uint32_t xa = (uint32_t)(((2 * ks + hi + a_add) ^ a_s) << 4);
            const uint32_t xb = (uint32_t)(((2 * ks + hb + b_add) ^ b_s) << 4);
            uint32_t a[2][4], b[2][4];
            #pragma unroll
            for (int mi = 0; mi < 2; mi++)
                ldsm_x4(a[mi], ab + (uint32_t)mi * 1024 + xa);
            #pragma unroll
            for (int pr = 0; pr < 2; pr++)
                ldsm_x4(b[pr], bb + (uint32_t)pr * 1024 + xb);

            #pragma unroll
            for (int mi = 0; mi < 2; mi++)
                #pragma unroll
                for (int qq = 0; qq < 4; qq++) a[mi][qq] = round_tf32(a[mi][qq]);
            #pragma unroll
            for (int pr = 0; pr < 2; pr++)
                #pragma unroll
                for (int qq = 0; qq < 4; qq++) b[pr][qq] = round_tf32(b[pr][qq]);

            #pragma unroll
            for (int mi = 0; mi < 2; mi++)
                #pragma unroll
                for (int ni = 0; ni < 4; ni++)
                    mma_tf32(acc[mi][ni], a[mi], &b[ni >> 1][(ni & 1) * 2]);
        }

        // position boundary: drain pos_a, start pos_b (loads already flowing)
        if (c == n1 - 1 && n2 > 0) {
            epilogue(p_a);
            init_acc(p_b);
        }
    }

    epilogue(n2 > 0 ? p_b : p_a);
}

extern "C" void kernel_launch(void* const* d_in, const int* in_sizes, int n_in,
                              void* d_out, int out_size)
{
    const float* x    = (const float*)d_in[0];  // (64,512,128)
    const float* w    = (const float*)d_in[1];  // (8,512,128,128)
    const float* bias = (const float*)d_in[2];  // (1030,128)
    float* y = (float*)d_out;                   // (64,1030,128)

    tdconv_tf32pp_kernel<<<GRID, 256, SMEM_TOTAL>>>(x, w, bias, y);
}

// round 16
// speedup vs baseline: 1.2130x; 1.2130x over previous
#include <cuda_runtime.h>
#include <cstdint>

// TransposeTDLayer via tf32 mma.sync + cp.async, K=16-stage QUAD buffer,
// issue-lead 2, XOR-swizzled packed smem, 4 CTAs/SM.
// Round-16 tune: all LDSM lane offsets fully precomputed (no per-iteration
// swizzle math); chunk loop unrolled x4 so buffer bases constant-fold.
// y[b,p,o] = bias[p,o] + sum_{(k,l):k+2l=p} sum_ci W[k,l,o,ci] * x[b,l,ci]
// tf32 rounding via +0x1000 (bit-exact vs cvt.rna.tf32, validated round 10).

#define BATCH 64
#define LIN   512
#define CIN   128
#define COUT  128
#define OUTP  1030

#define A_OFF   0
#define A_BYTES 8192                       // 128 rows x 64B packed
#define B_OFF   A_BYTES
#define B_BYTES 4096                       // 64 rows x 64B packed
#define BUF_BYTES (A_BYTES + B_BYTES)      // 12288
#define NSTAGE  4
#define SMEM_TOTAL (NSTAGE * BUF_BYTES)    // 49152/CTA -> 4 CTAs/SM

static __device__ __forceinline__ uint32_t smem_u32(const void* p) {
    uint32_t a;
    asm("{ .reg .u64 t; cvta.to.shared.u64 t, %1; cvt.u32.u64 %0, t; }"
        : "=r"(a) : "l"(p));
    return a;
}

static __device__ __forceinline__ void mma_tf32(
    float* c, const uint32_t* a, const uint32_t* b)
{
    asm volatile(
        "mma.sync.aligned.m16n8k8.row.col.f32.tf32.tf32.f32 "
        "{%0,%1,%2,%3}, {%4,%5,%6,%7}, {%8,%9}, {%0,%1,%2,%3};"
        : "+f"(c[0]), "+f"(c[1]), "+f"(c[2]), "+f"(c[3])
        : "r"(a[0]), "r"(a[1]), "r"(a[2]), "r"(a[3]), "r"(b[0]), "r"(b[1]));
}

static __device__ __forceinline__ void ldsm_x4(uint32_t* r, uint32_t addr) {
    asm volatile("ldmatrix.sync.aligned.m8n8.x4.shared.b16 {%0,%1,%2,%3}, [%4];"
                 : "=r"(r[0]), "=r"(r[1]), "=r"(r[2]), "=r"(r[3]) : "r"(addr));
}

// tf32 round-to-nearest via +half-ulp; tensor core truncates low 13 bits.
static __device__ __forceinline__ uint32_t round_tf32(uint32_t v) {
    return v + 0x1000u;
}

static __device__ __forceinline__ void cpasync16(uint32_t dst, const void* src) {
    asm volatile("cp.async.cg.shared.global [%0], [%1], 16;"
                 :: "r"(dst), "l"(src) : "memory");
}
#define CP_COMMIT() asm volatile("cp.async.commit_group;" ::: "memory")
#define CP_WAIT2()  asm volatile("cp.async.wait_group 2;" ::: "memory")

// swizzled byte offset of 16B granule g (0..3) in 64B row r
static __device__ __forceinline__ uint32_t sw_off(int r, int g) {
    return (uint32_t)((r >> 1) * 128 + (((g + (r & 1) * 4) ^ ((r >> 1) & 7)) << 4));
}

__global__ void __launch_bounds__(256, 4)
tdconv_tf32t_kernel(const float* __restrict__ x,
                    const float* __restrict__ w,
                    const float* __restrict__ bias,
                    float* __restrict__ y)
{
    extern __shared__ char smem[];
    const uint32_t sbase = smem_u32(smem);

    const int p    = blockIdx.x;
    const int tid  = threadIdx.x;
    const int wid  = tid >> 5;
    const int lane = tid & 31;

    const int mrow = (wid >> 1) * 32;   // cout base (0,32,64,96)
    const int ncol = (wid & 1) * 32;    // batch base (0,32)

    // contributing blocks: k = par + 2j, l = m - j, j in [j0, j1]
    const int par = p & 1;
    const int m   = (p - par) >> 1;
    int j0 = m - (LIN - 1); if (j0 < 0) j0 = 0;
    int j1 = m < 3 ? m : 3;
    const int nblk    = j1 - j0 + 1;
    const int nchunks = 8 * nblk;       // K=16 slices; always multiple of 8

    // producer decomposition: thread -> (row cr 0..63, granule cg 0..3)
    const int cr = tid >> 2;
    const int cg = tid & 3;
    const uint32_t d0 = sw_off(cr, cg);

    // issue cp.async for chunk c (block c>>3, K-slice c&7) into buf[c&3]
    auto issue_chunk = [&](int c) {
        if (c < nchunks) {
            const int j = j0 + (c >> 3);
            const int l = m - j;
            const int k = par + 2 * j;
            const int kh = (c & 7) * 16;
            const float* __restrict__ wp =
                w + (size_t)(k * LIN + l) * (COUT * CIN)
                  + (size_t)cr * CIN + kh + cg * 4;
            const float* __restrict__ xp =
                x + ((size_t)cr * LIN + l) * CIN + kh + cg * 4;
            const uint32_t buf = sbase + (uint32_t)(c & 3) * BUF_BYTES;
            cpasync16(buf + A_OFF + d0,        wp);
            cpasync16(buf + A_OFF + d0 + 4096, wp + 64 * CIN);
            cpasync16(buf + B_OFF + d0,        xp);
        }
        CP_COMMIT();   // uniform group counting
    };

    // ---- fully precomputed LDSM lane offsets (loop-invariant) ----
    const int q   = (lane & 7) + ((lane >> 3) & 1) * 8;   // A row-in-tile
    const int hi  = lane >> 4;                            // A k-granule half
    const uint32_t a_line = (uint32_t)(mrow / 2 + (q >> 1)) * 128;
    const int a_add = (q & 1) * 4, a_s = q >> 1;
    const uint32_t aoff0 = A_OFF + a_line
        + (uint32_t)(((0 + hi + a_add) ^ a_s) << 4);      // ks=0
    const uint32_t aoff1 = A_OFF + a_line
        + (uint32_t)(((2 + hi + a_add) ^ a_s) << 4);      // ks=1

    const int qb  = (lane & 7) + (lane >> 4) * 8;         // B row-in-tile
    const int hb  = (lane >> 3) & 1;                      // B k-granule half
    const uint32_t b_line = (uint32_t)(ncol / 2 + (qb >> 1)) * 128;
    const int b_add = (qb & 1) * 4, b_s = qb >> 1;
    const uint32_t boff0 = B_OFF + b_line
        + (uint32_t)(((0 + hb + b_add) ^ b_s) << 4);
    const uint32_t boff1 = B_OFF + b_line
        + (uint32_t)(((2 + hb + b_add) ^ b_s) << 4);

    // accumulators init with bias (same across batch cols)
    const int g = lane >> 2;
    float acc[2][4][4];
    #pragma unroll
    for (int mi = 0; mi < 2; mi++) {
        const float b_g  = bias[p * COUT + mrow + mi * 16 + g];
        const float b_g8 = bias[p * COUT + mrow + mi * 16 + g + 8];
        #pragma unroll
        for (int ni = 0; ni < 4; ni++) {
            acc[mi][ni][0] = b_g;  acc[mi][ni][1] = b_g;
            acc[mi][ni][2] = b_g8; acc[mi][ni][3] = b_g8;
        }
    }

    // prologue: 3 chunks in flight
    issue_chunk(0);
    issue_chunk(1);
    issue_chunk(2);

    // main loop unrolled x4: nchunks % 8 == 0, so c & 3 == u (constant-folds
    // the stage-buffer base per unrolled body)
    for (int c0 = 0; c0 < nchunks; c0 += 4) {
        #pragma unroll
        for (int u = 0; u < 4; u++) {
            const int c = c0 + u;
            CP_WAIT2();               // chunk c retired (c+1, c+2 pending ok)
            __syncthreads();          // chunk c visible; buf[(c+3)&3] reusable

            issue_chunk(c + 3);       // refill BEFORE compute

            const uint32_t buf = sbase + (uint32_t)u * BUF_BYTES;

            uint32_t a[2][4], b[2][4];
            // ---- ks = 0 ----
            ldsm_x4(a[0], buf + aoff0);
            ldsm_x4(a[1], buf + aoff0 + 1024);
            ldsm_x4(b[0], buf + boff0);
            ldsm_x4(b[1], buf + boff0 + 1024);
            #pragma unroll
            for (int mi = 0; mi < 2; mi++)
                #pragma unroll
                for (int qq = 0; qq < 4; qq++) a[mi][qq] = round_tf32(a[mi][qq]);
            #pragma unroll
            for (int pr = 0; pr < 2; pr++)
                #pragma unroll
                for (int qq = 0; qq < 4; qq++) b[pr][qq] = round_tf32(b[pr][qq]);
            #pragma unroll
            for (int mi = 0; mi < 2; mi++)
                #pragma unroll
                for (int ni = 0; ni < 4; ni++)
                    mma_tf32(acc[mi][ni], a[mi], &b[ni >> 1][(ni & 1) * 2]);

            // ---- ks = 1 ----
            ldsm_x4(a[0], buf + aoff1);
            ldsm_x4(a[1], buf + aoff1 + 1024);
            ldsm_x4(b[0], buf + boff1);
            ldsm_x4(b[1], buf + boff1 + 1024);
            #pragma unroll
            for (int mi = 0; mi < 2; mi++)
                #pragma unroll
                for (int qq = 0; qq < 4; qq++) a[mi][qq] = round_tf32(a[mi][qq]);
            #pragma unroll
            for (int pr = 0; pr < 2; pr++)
                #pragma unroll
                for (int qq = 0; qq < 4; qq++) b[pr][qq] = round_tf32(b[pr][qq]);
            #pragma unroll
            for (int mi = 0; mi < 2; mi++)
                #pragma unroll
                for (int ni = 0; ni < 4; ni++)
                    mma_tf32(acc[mi][ni], a[mi], &b[ni >> 1][(ni & 1) * 2]);
        }
    }

    // ---- epilogue: D[o,b] -> y[b,p,o] ----
    const int t = lane & 3;
    #pragma unroll
    for (int mi = 0; mi < 2; mi++) {
        const int o0 = mrow + mi * 16 + g;
        const int o8 = o0 + 8;
        #pragma unroll
        for (int ni = 0; ni < 4; ni++) {
            const int b0 = ncol + ni * 8 + 2 * t;
            float* y0 = y + ((size_t)b0 * OUTP + p) * COUT;
            float* y1 = y0 + (size_t)OUTP * COUT;
            y0[o0] = acc[mi][ni][0];
            y1[o0] = acc[mi][ni][1];
            y0[o8] = acc[mi][ni][2];
            y1[o8] = acc[mi][ni][3];
        }
    }
}

extern "C" void kernel_launch(void* const* d_in, const int* in_sizes, int n_in,
                              void* d_out, int out_size)
{
    const float* x    = (const float*)d_in[0];  // (64,512,128)
    const float* w    = (const float*)d_in[1];  // (8,512,128,128)
    const float* bias = (const float*)d_in[2];  // (1030,128)
    float* y = (float*)d_out;                   // (64,1030,128)

    tdconv_tf32t_kernel<<<OUTP, 256, SMEM_TOTAL>>>(x, w, bias, y);
}